// round 17
// baseline (speedup 1.0000x reference)
#include <cuda_runtime.h>
#include <stdint.h>

typedef unsigned long long ull;

#define KBOX 256
#define CCH  512
#define NTOK 1024
#define HH   32
#define OSZ  7
#define KDIM (CCH * OSZ * OSZ)          // 25088
#define BM   128
#define BN   128
#define BK   8
#define SPLITK 32
#define KSPLIT (KDIM / SPLITK)          // 784
#define KITER  (KSPLIT / BK)            // 98

// f32 round-to-nearest of 1/7 (0x3E124925) — XLA rewrites x/7 to x*(1/7)
#define RECIP7 0.14285715f
#define NEGINF (-3.402823466e38f)

// Scratch (static __device__ arrays: allocation-free per harness rules)
__device__ __align__(16) float g_pool[(size_t)KBOX * KDIM];           // 25.7 MB
__device__ __align__(16) float g_part[(size_t)SPLITK * KBOX * CCH];   // 16.8 MB

// ---- f32x2 packed-FMA helpers (numerically validated vs scalar SGEMM) ----
__device__ __forceinline__ ull dup2(float v) {
    ull d; asm("mov.b64 %0, {%1, %1};" : "=l"(d) : "f"(v)); return d;
}
__device__ __forceinline__ ull fma2(ull a, ull b, ull c) {
    ull d; asm("fma.rn.f32x2 %0, %1, %2, %3;" : "=l"(d) : "l"(a), "l"(b), "l"(c)); return d;
}
__device__ __forceinline__ void unpack2(ull v, float& lo, float& hi) {
    asm("mov.b64 {%0, %1}, %2;" : "=f"(lo), "=f"(hi) : "l"(v));
}

// ============================================================================
// Stage 1: ROI max pool — R13 version VERBATIM (79 µs measured; the R16
// "ILP" restructure regressed to 93 µs via 128 regs / 21% occupancy).
// One thread per (box, channel); 49 bins serially.
// bin_sz = roi * rn(1/7) — matches XLA's reciprocal canonicalization (KEY).
// ============================================================================
__global__ void pool_kernel(const float* __restrict__ x,
                            const float* __restrict__ boxes) {
    const int k = blockIdx.x;
    const int c = threadIdx.x;

    const int   b  = (int)boxes[k * 5 + 0];
    const float x1 = rintf(boxes[k * 5 + 1] * 32.0f);   // *32 exact (2^5)
    const float y1 = rintf(boxes[k * 5 + 2] * 32.0f);
    const float x2 = rintf(boxes[k * 5 + 3] * 32.0f);
    const float y2 = rintf(boxes[k * 5 + 4] * 32.0f);
    const float rw = fmaxf(x2 - x1 + 1.0f, 1.0f);
    const float rh = fmaxf(y2 - y1 + 1.0f, 1.0f);
    const float bw = __fmul_rn(rw, RECIP7);   // reciprocal-multiply, like XLA
    const float bh = __fmul_rn(rh, RECIP7);

    int xlo[OSZ], xhi[OSZ], ylo[OSZ], yhi[OSZ];
#pragma unroll
    for (int p = 0; p < OSZ; p++) {
        float pf = (float)p;
        float lo = floorf(__fmul_rn(pf, bw)) + x1;
        float hi = ceilf(__fmul_rn(pf + 1.0f, bw)) + x1;
        lo = fminf(fmaxf(lo, 0.0f), 32.0f);
        hi = fminf(fmaxf(hi, 0.0f), 32.0f);
        xlo[p] = (int)lo; xhi[p] = (int)hi;
        lo = floorf(__fmul_rn(pf, bh)) + y1;
        hi = ceilf(__fmul_rn(pf + 1.0f, bh)) + y1;
        lo = fminf(fmaxf(lo, 0.0f), 32.0f);
        hi = fminf(fmaxf(hi, 0.0f), 32.0f);
        ylo[p] = (int)lo; yhi[p] = (int)hi;
    }

    // feat[b,c,h,w] = x[b, h*32+w, c]
    const float* xb   = x + (size_t)b * NTOK * CCH + c;
    float*       outp = g_pool + (size_t)k * KDIM + (size_t)c * (OSZ * OSZ);

    for (int i = 0; i < OSZ; i++) {          // i = row bin (y/h)
        const int h0 = ylo[i], h1 = yhi[i];
        for (int j = 0; j < OSZ; j++) {      // j = col bin (x/w)
            const int w0 = xlo[j], w1 = xhi[j];
            float m = NEGINF;
            for (int h = h0; h < h1; h++) {
                const float* row = xb + (size_t)(h * HH) * CCH;
                for (int w = w0; w < w1; w++)
                    m = fmaxf(m, row[(size_t)w * CCH]);
            }
            if (h1 <= h0 || w1 <= w0) m = 0.0f;   // empty bin -> 0
            outp[i * OSZ + j] = m;
        }
    }
}

// ============================================================================
// Stage 2: split-K GEMM  part[s] = pool(256 x Ks) * conv_w^T(Ks x 512)
// 128x128x8 tiles, 256 threads, 8x8 micro-tile, double-buffered smem.
// R16 limiter was smem BW (A stored as dup (a,a) pairs -> 6 LDS.128/kk,
// 384 crossbar-cyc vs 256 fma-cyc per SM). Now A is stored as plain floats:
// 4 LDS.128/kk (256 cyc) + 8 ALU movs to build (a,a) packs -> fma-limited.
// ============================================================================
__global__ __launch_bounds__(256, 2) void gemm_kernel(const float* __restrict__ conv_w) {
    __shared__ __align__(16) float As[2][BK][BM + 4];   // plain floats, row 528B
    __shared__ __align__(16) float Bs[2][BK][BN + 4];   // row 528B

    const int tid  = threadIdx.x;
    const int n0   = blockIdx.x * BN;
    const int m0   = blockIdx.y * BM;
    const int kbeg = blockIdx.z * KSPLIT;

    const int lrow = tid >> 1;          // 0..127
    const int lk4  = (tid & 1) * 4;     // 0,4
    const int ty8  = (tid >> 4) * 8;    // 0..120
    const int tx8  = (tid & 15) * 8;    // 0..120

    const float* Ag = g_pool + (size_t)(m0 + lrow) * KDIM + kbeg + lk4;
    const float* Bg = conv_w + (size_t)(n0 + lrow) * KDIM + kbeg + lk4;

    ull acc[8][4];
#pragma unroll
    for (int r = 0; r < 8; r++)
#pragma unroll
        for (int q = 0; q < 4; q++) acc[r][q] = 0ull;

    // prefetch kt=0
    float4 av = *(const float4*)Ag;
    float4 bv = *(const float4*)Bg;

    int p = 0;
    for (int kt = 0; kt < KITER; kt++) {
        As[p][lk4 + 0][lrow] = av.x;
        As[p][lk4 + 1][lrow] = av.y;
        As[p][lk4 + 2][lrow] = av.z;
        As[p][lk4 + 3][lrow] = av.w;
        Bs[p][lk4 + 0][lrow] = bv.x;
        Bs[p][lk4 + 1][lrow] = bv.y;
        Bs[p][lk4 + 2][lrow] = bv.z;
        Bs[p][lk4 + 3][lrow] = bv.w;
        __syncthreads();

        if (kt + 1 < KITER) {            // prefetch next K-step (LDG hidden)
            Ag += BK; Bg += BK;
            av = *(const float4*)Ag;
            bv = *(const float4*)Bg;
        }

#pragma unroll
        for (int kk = 0; kk < BK; kk++) {
            const float4 af0 = *(const float4*)&As[p][kk][ty8];
            const float4 af1 = *(const float4*)&As[p][kk][ty8 + 4];
            const ulonglong2 b01 = *(const ulonglong2*)&Bs[p][kk][tx8];
            const ulonglong2 b23 = *(const ulonglong2*)&Bs[p][kk][tx8 + 4];
            const ull a[8] = {dup2(af0.x), dup2(af0.y), dup2(af0.z), dup2(af0.w),
                              dup2(af1.x), dup2(af1.y), dup2(af1.z), dup2(af1.w)};
            const ull bb[4] = {b01.x, b01.y, b23.x, b23.y};
#pragma unroll
            for (int r = 0; r < 8; r++)
#pragma unroll
                for (int q = 0; q < 4; q++)
                    acc[r][q] = fma2(a[r], bb[q], acc[r][q]);
        }
        p ^= 1;
    }

    float* P = g_part + (size_t)blockIdx.z * KBOX * CCH;
#pragma unroll
    for (int r = 0; r < 8; r++) {
        float4 v0, v1;
        unpack2(acc[r][0], v0.x, v0.y);
        unpack2(acc[r][1], v0.z, v0.w);
        unpack2(acc[r][2], v1.x, v1.y);
        unpack2(acc[r][3], v1.z, v1.w);
        float* dst = &P[(size_t)(m0 + ty8 + r) * CCH + n0 + tx8];
        *(float4*)dst       = v0;
        *(float4*)(dst + 4) = v1;
    }
}

// ============================================================================
// Stage 3: reduce split-K partials + bias -> out (256 x 512), deterministic.
// ============================================================================
__global__ __launch_bounds__(256) void reduce_kernel(const float* __restrict__ bias,
                                                     float* __restrict__ out) {
    const int idx = blockIdx.x * blockDim.x + threadIdx.x;
    if (idx >= KBOX * CCH) return;
    float sum = bias[idx & (CCH - 1)];
#pragma unroll
    for (int p = 0; p < SPLITK; p++)
        sum += g_part[(size_t)p * KBOX * CCH + idx];
    out[idx] = sum;
}

extern "C" void kernel_launch(void* const* d_in, const int* in_sizes, int n_in,
                              void* d_out, int out_size) {
    // Select inputs by element count (robust to metadata ordering):
    // x=4194304, boxes=1280, box_labels=256, conv_w=12845056, conv_b=512
    const float* x      = nullptr;
    const float* boxes  = nullptr;
    const float* conv_w = nullptr;
    const float* conv_b = nullptr;
    for (int i = 0; i < n_in; i++) {
        switch (in_sizes[i]) {
            case 4194304:  x      = (const float*)d_in[i]; break;
            case 1280:     boxes  = (const float*)d_in[i]; break;
            case 12845056: conv_w = (const float*)d_in[i]; break;
            case 512:      conv_b = (const float*)d_in[i]; break;
            default: break;                    // box_labels (256): unused
        }
    }
    float* out = (float*)d_out;
    const size_t NX = 4194304;

    // Output layout: (x passthrough, box_feats)
    cudaMemcpyAsync(out, x, NX * sizeof(float), cudaMemcpyDeviceToDevice, 0);

    pool_kernel<<<KBOX, CCH>>>(x, boxes);     // R13 config: 256 blocks x 512

    dim3 grid(CCH / BN, KBOX / BM, SPLITK);   // (4, 2, 32) = 256 CTAs
    gemm_kernel<<<grid, 256>>>(conv_w);

    reduce_kernel<<<(KBOX * CCH + 255) / 256, 256>>>(conv_b, out + NX);
}